// round 8
// baseline (speedup 1.0000x reference)
#include <cuda_runtime.h>

#define NN 50000
#define EE 800000
#define ETOT (EE + NN)

// ---------------- scratch (static device arrays; no runtime allocation) ----
__device__ int   g_csrc[ETOT];
__device__ int   g_cnt[NN];        // zero-initialized; k_scatter re-zeros each call
__device__ int   g_rowstart[NN + 1];
__device__ int   g_wptr[NN];
__device__ float g_xw1[NN * 128];
__device__ float g_as1[NN * 4];
__device__ float g_ad1[NN * 4];
__device__ float g_xw2[NN * 8];
__device__ float g_as2[NN];
__device__ float g_ad2[NN];

// ---------------- CSR build ------------------------------------------------
// edge_index is INT32 (JAX x64 disabled makes the reference's astype(int64) a no-op)
__global__ void k_edges(const int* __restrict__ ei, int E) {
    int i = blockIdx.x * blockDim.x + threadIdx.x;
    if (i >= E) return;
    atomicAdd(&g_cnt[ei[E + i]], 1);
}

// single-kernel scan, reset-free: block b sums ALL preceding counts itself
// (~20MB of coalesced L2 reads total -> ~2us), then scans its own 256-tile.
// Self loops folded in as +1 per node. Does NOT modify g_cnt (k_scatter does).
__global__ void k_scan(int N, int T) {
    __shared__ int ws[8];
    __shared__ int s_off;
    int b = blockIdx.x, t = threadIdx.x, lane = t & 31, w = t >> 5;
    int base = b * 256;

    // phase 1: offset = sum of counts of nodes [0, base) + base self loops
    int partial = 0;
    for (int j = t; j < base; j += 256) partial += g_cnt[j];
    #pragma unroll
    for (int o = 16; o; o >>= 1) partial += __shfl_xor_sync(0xffffffffu, partial, o);
    if (lane == 0) ws[w] = partial;
    __syncthreads();
    if (w == 0) {
        int s = (lane < 8) ? ws[lane] : 0;
        #pragma unroll
        for (int o = 4; o; o >>= 1) s += __shfl_xor_sync(0xffffffffu, s, o);
        if (lane == 0) s_off = s + base;
    }
    __syncthreads();
    int off = s_off;
    __syncthreads();                   // ws reuse hazard fence

    // phase 2: exclusive scan of own tile (count+1 per node)
    int i = base + t;
    int v = (i < N) ? (g_cnt[i] + 1) : 0;
    int x = v;
    #pragma unroll
    for (int o = 1; o < 32; o <<= 1) {
        int y = __shfl_up_sync(0xffffffffu, x, o);
        if (lane >= o) x += y;
    }
    if (lane == 31) ws[w] = x;
    __syncthreads();
    if (w == 0) {
        int s = (lane < 8) ? ws[lane] : 0;
        #pragma unroll
        for (int o = 1; o < 8; o <<= 1) {
            int y = __shfl_up_sync(0xffffffffu, s, o);
            if (lane >= o) s += y;
        }
        if (lane < 8) ws[lane] = s;
    }
    __syncthreads();
    int excl = off + (x - v) + (w ? ws[w - 1] : 0);
    if (i < N) { g_rowstart[i] = excl; g_wptr[i] = excl; }
    if (b == 0 && t == 0) g_rowstart[N] = T;
}

// scatter straight from edge_index; ILP-2 (two independent atomic chains per
// thread); also restores g_cnt to zero for the next graph replay.
__global__ void k_scatter(const int* __restrict__ ei, int E, int T, int N, int half) {
    int i = blockIdx.x * blockDim.x + threadIdx.x;
    if (i < N) g_cnt[i] = 0;
    if (i >= half) return;
    int i1 = i + half;
    int s0, d0;
    if (i < E) { s0 = ei[i]; d0 = ei[E + i]; }
    else       { s0 = d0 = i - E; }
    int p0 = atomicAdd(&g_wptr[d0], 1);
    if (i1 < T) {
        int s1, d1;
        if (i1 < E) { s1 = ei[i1]; d1 = ei[E + i1]; }
        else        { s1 = d1 = i1 - E; }
        int p1 = atomicAdd(&g_wptr[d1], 1);
        g_csrc[p1] = s1;
    }
    g_csrc[p0] = s0;
}

// ---------------- layer-1 GEMM: xw1 = x @ W1 (+ attention dots) ------------
// 256 threads/block, 128 nodes/block. W1 transposed in smem (pitch 132).
// Packed fma.rn.f32x2 (dual fp32 FMA) halves fma-pipe occupancy.
extern __shared__ float sm_g1[];
__global__ void k_gemm1(const float* __restrict__ x, const float* __restrict__ W1,
                        const float* __restrict__ as1, const float* __restrict__ ad1,
                        int N) {
    float* Wt = sm_g1;                 // 128 cols x pitch 132
    float* xs = sm_g1 + 128 * 132;     // 16 x 128
    int t = threadIdx.x;
    int col = t & 127, grp = t >> 7, lane = t & 31;
    for (int idx = t; idx < 128 * 128; idx += 256) {
        int k = idx >> 7, c = idx & 127;
        Wt[c * 132 + k] = W1[idx];
    }
    float at_s = as1[col], at_d = ad1[col];
    __syncthreads();

    int nb = blockIdx.x * 128;
    for (int b = 0; b < 8; b++) {
        int base = nb + b * 16;
        for (int idx = t; idx < 16 * 128; idx += 256) {
            int m = idx >> 7, k = idx & 127;
            int nn = base + m;
            xs[idx] = (nn < N) ? x[nn * 128 + k] : 0.f;
        }
        __syncthreads();
        const float* xg = xs + grp * 8 * 128;
        unsigned long long acc2[8];
        #pragma unroll
        for (int m = 0; m < 8; m++) acc2[m] = 0ull;   // (0.f, 0.f)
        for (int k = 0; k < 128; k += 4) {
            float4 wv = *(const float4*)&Wt[col * 132 + k];
            unsigned long long w01, w23;
            asm("mov.b64 %0,{%1,%2};" : "=l"(w01) : "f"(wv.x), "f"(wv.y));
            asm("mov.b64 %0,{%1,%2};" : "=l"(w23) : "f"(wv.z), "f"(wv.w));
            #pragma unroll
            for (int m = 0; m < 8; m++) {
                float4 xv = *(const float4*)&xg[m * 128 + k];
                unsigned long long x01, x23;
                asm("mov.b64 %0,{%1,%2};" : "=l"(x01) : "f"(xv.x), "f"(xv.y));
                asm("mov.b64 %0,{%1,%2};" : "=l"(x23) : "f"(xv.z), "f"(xv.w));
                asm("fma.rn.f32x2 %0,%1,%2,%3;"
                    : "=l"(acc2[m]) : "l"(x01), "l"(w01), "l"(acc2[m]));
                asm("fma.rn.f32x2 %0,%1,%2,%3;"
                    : "=l"(acc2[m]) : "l"(x23), "l"(w23), "l"(acc2[m]));
            }
        }
        int n0 = base + grp * 8;
        #pragma unroll
        for (int m = 0; m < 8; m++) {
            float lo, hi;
            asm("mov.b64 {%0,%1},%2;" : "=f"(lo), "=f"(hi) : "l"(acc2[m]));
            float accm = lo + hi;
            int n = n0 + m;
            float sv = accm * at_s, dv = accm * at_d;
            #pragma unroll
            for (int o = 16; o; o >>= 1) {
                sv += __shfl_down_sync(0xffffffffu, sv, o);
                dv += __shfl_down_sync(0xffffffffu, dv, o);
            }
            if (n < N) {
                g_xw1[n * 128 + col] = accm;
                if (lane == 0) {
                    int h = (t >> 5) & 3;
                    g_as1[n * 4 + h] = sv;
                    g_ad1[n * 4 + h] = dv;
                }
            }
        }
        __syncthreads();
    }
}

// ---------------- layer-1 gather: softmax + fused bias/relu/GEMM2 ----------
// One warp per destination node. Lane = (head h=lane>>3, slot j=lane&7).
// Per 8-edge chunk: each lane computes e/p for ONE (edge,head) pair -> 1 expf
// per 8 edges (vs 8 redundant before); p/s shuffled to accumulating lanes,
// which own channels [lane*4, lane*4+4) of the same head h.
__global__ void k_gather1(const float* __restrict__ b1, const float* __restrict__ W2,
                          const float* __restrict__ as2v, const float* __restrict__ ad2v,
                          int N) {
    int t = threadIdx.x, lane = t & 31;
    int n = blockIdx.x * 8 + (t >> 5);
    if (n >= N) return;

    int c0 = lane * 4;          // flat channel base
    int h = lane >> 3;          // head for both phases (c0/32 == lane>>3)
    int j = lane & 7;           // edge slot within chunk
    float4 wA[4], wB[4];
    #pragma unroll
    for (int jj = 0; jj < 4; jj++) {
        wA[jj] = *(const float4*)&W2[(c0 + jj) * 8];
        wB[jj] = *(const float4*)&W2[(c0 + jj) * 8 + 4];
    }
    float4 b1v = *(const float4*)&b1[c0];
    float adh = g_ad1[n * 4 + h];

    float den = 0.f;
    float4 acc = make_float4(0.f, 0.f, 0.f, 0.f);
    int beg = g_rowstart[n], end = g_rowstart[n + 1];
    for (int i = beg; i < end; i += 8) {
        int idx = i + j;
        bool v = (idx < end);
        int s = v ? g_csrc[idx] : 0;
        float e = v ? (g_as1[s * 4 + h] + adh) : -1e30f;
        e = fmaxf(e, 0.f) + 0.2f * fminf(e, 0.f);       // leaky relu
        float p = __expf(e);                            // 0 for masked slots
        den += p;                                       // lane-local partial
        #pragma unroll
        for (int jj = 0; jj < 8; jj++) {
            float pj = __shfl_sync(0xffffffffu, p, (lane & 24) + jj);
            int   sj = __shfl_sync(0xffffffffu, s, (lane & 24) + jj);
            float4 xv = *(const float4*)&g_xw1[sj * 128 + c0];
            acc.x += pj * xv.x; acc.y += pj * xv.y;
            acc.z += pj * xv.z; acc.w += pj * xv.w;
        }
    }
    // den: sum the 8 slot-partials within this head's lane group
    #pragma unroll
    for (int o = 4; o; o >>= 1) den += __shfl_xor_sync(0xffffffffu, den, o);

    float inv = 1.f / den;
    float hj[4];
    hj[0] = fmaxf(acc.x * inv + b1v.x, 0.f);
    hj[1] = fmaxf(acc.y * inv + b1v.y, 0.f);
    hj[2] = fmaxf(acc.z * inv + b1v.z, 0.f);
    hj[3] = fmaxf(acc.w * inv + b1v.w, 0.f);

    float4 pA = make_float4(0.f, 0.f, 0.f, 0.f);
    float4 pB = make_float4(0.f, 0.f, 0.f, 0.f);
    #pragma unroll
    for (int jj = 0; jj < 4; jj++) {
        pA.x += hj[jj] * wA[jj].x;  pA.y += hj[jj] * wA[jj].y;
        pA.z += hj[jj] * wA[jj].z;  pA.w += hj[jj] * wA[jj].w;
        pB.x += hj[jj] * wB[jj].x;  pB.y += hj[jj] * wB[jj].y;
        pB.z += hj[jj] * wB[jj].z;  pB.w += hj[jj] * wB[jj].w;
    }
    #pragma unroll
    for (int o = 16; o; o >>= 1) {
        pA.x += __shfl_xor_sync(0xffffffffu, pA.x, o);
        pA.y += __shfl_xor_sync(0xffffffffu, pA.y, o);
        pA.z += __shfl_xor_sync(0xffffffffu, pA.z, o);
        pA.w += __shfl_xor_sync(0xffffffffu, pA.w, o);
        pB.x += __shfl_xor_sync(0xffffffffu, pB.x, o);
        pB.y += __shfl_xor_sync(0xffffffffu, pB.y, o);
        pB.z += __shfl_xor_sync(0xffffffffu, pB.z, o);
        pB.w += __shfl_xor_sync(0xffffffffu, pB.w, o);
    }
    if (lane == 0) {
        *(float4*)&g_xw2[n * 8]     = pA;
        *(float4*)&g_xw2[n * 8 + 4] = pB;
        float4 sA = *(const float4*)&as2v[0];
        float4 sB = *(const float4*)&as2v[4];
        float4 dA = *(const float4*)&ad2v[0];
        float4 dB = *(const float4*)&ad2v[4];
        g_as2[n] = pA.x * sA.x + pA.y * sA.y + pA.z * sA.z + pA.w * sA.w
                 + pB.x * sB.x + pB.y * sB.y + pB.z * sB.z + pB.w * sB.w;
        g_ad2[n] = pA.x * dA.x + pA.y * dA.y + pA.z * dA.z + pA.w * dA.w
                 + pB.x * dB.x + pB.y * dB.y + pB.z * dB.z + pB.w * dB.w;
    }
}

// ---------------- layer-2 gather + bias + log_softmax ----------------------
// 8 lanes per node; each lane handles a different edge in a chunk of 8.
// Unshifted softmax: 1 expf + 1 sub-warp sum per 8 edges.
__global__ void k_gather2(const float* __restrict__ b2, float* __restrict__ out, int N) {
    int t = blockIdx.x * blockDim.x + threadIdx.x;
    int n = t >> 3, sub = t & 7;
    if (n >= N) return;
    unsigned gm = 0xffu << ((threadIdx.x & 31) & 24);   // this 8-lane group's mask

    float adh = g_ad2[n];
    float den = 0.f, acc = 0.f;
    int beg = g_rowstart[n], end = g_rowstart[n + 1];
    for (int i = beg; i < end; i += 8) {
        int idx = i + sub;
        bool v = (idx < end);
        int s = v ? g_csrc[idx] : 0;
        float e = v ? (g_as2[s] + adh) : -1e30f;
        e = fmaxf(e, 0.f) + 0.2f * fminf(e, 0.f);
        float p = __expf(e);                       // 0 for invalid lanes
        float psum = p;
        #pragma unroll
        for (int o = 4; o; o >>= 1)
            psum += __shfl_xor_sync(gm, psum, o, 8);
        den += psum;
        #pragma unroll
        for (int jj = 0; jj < 8; jj++) {
            float pj = __shfl_sync(gm, p, jj, 8);
            int   sj = __shfl_sync(gm, s, jj, 8);
            acc += pj * g_xw2[sj * 8 + sub];
        }
    }
    float o = acc / den + b2[sub];
    float m8 = o;
    #pragma unroll
    for (int off = 4; off; off >>= 1)
        m8 = fmaxf(m8, __shfl_xor_sync(gm, m8, off, 8));
    float ex = __expf(o - m8), sum = ex;
    #pragma unroll
    for (int off = 4; off; off >>= 1)
        sum += __shfl_xor_sync(gm, sum, off, 8);
    out[n * 8 + sub] = o - m8 - logf(sum);
}

// ---------------- launch ---------------------------------------------------
extern "C" void kernel_launch(void* const* d_in, const int* in_sizes, int n_in,
                              void* d_out, int out_size) {
    const float* x   = (const float*)d_in[0];
    const int*   ei  = (const int*)d_in[1];        // int32! (JAX x64 disabled)
    const float* W1  = (const float*)d_in[2];
    const float* as1 = (const float*)d_in[3];
    const float* ad1 = (const float*)d_in[4];
    const float* b1  = (const float*)d_in[5];
    const float* W2  = (const float*)d_in[6];
    const float* as2 = (const float*)d_in[7];
    const float* ad2 = (const float*)d_in[8];
    const float* b2  = (const float*)d_in[9];

    int N = in_sizes[0] / 128;
    int E = in_sizes[1] / 2;
    int T = E + N;
    int nb = (N + 255) / 256;
    int half = (T + 1) / 2;

    // fork: gemm1 (needs only raw inputs) runs concurrently with the CSR build.
    cudaStream_t s2;
    cudaEvent_t ev_fork, ev_join;
    cudaStreamCreateWithFlags(&s2, cudaStreamNonBlocking);
    cudaEventCreateWithFlags(&ev_fork, cudaEventDisableTiming);
    cudaEventCreateWithFlags(&ev_join, cudaEventDisableTiming);

    cudaEventRecord(ev_fork, 0);
    cudaStreamWaitEvent(s2, ev_fork, 0);

    int smem = (128 * 132 + 16 * 128) * (int)sizeof(float);
    cudaFuncSetAttribute(k_gemm1, cudaFuncAttributeMaxDynamicSharedMemorySize, smem);
    k_gemm1<<<(N + 127) / 128, 256, smem, s2>>>(x, W1, as1, ad1, N);
    cudaEventRecord(ev_join, s2);

    // CSR build on the default stream (g_cnt is zero: static init on first
    // call, re-zeroed by k_scatter on every call)
    k_edges<<<(E + 255) / 256, 256>>>(ei, E);
    k_scan<<<nb, 256>>>(N, T);
    k_scatter<<<(half + 255) / 256, 256>>>(ei, E, T, N, half);

    cudaStreamWaitEvent(0, ev_join, 0);     // join gemm1 before gather1
    k_gather1<<<(N + 7) / 8, 256>>>(b1, W2, as2, ad2, N);
    k_gather2<<<(N * 8 + 255) / 256, 256>>>(b2, (float*)d_out, N);

    cudaStreamDestroy(s2);
    cudaEventDestroy(ev_fork);
    cudaEventDestroy(ev_join);
}

// round 9
// speedup vs baseline: 1.0680x; 1.0680x over previous
#include <cuda_runtime.h>

#define NN 50000
#define EE 800000
#define ETOT (EE + NN)

// ---------------- scratch (static device arrays; no runtime allocation) ----
__device__ int      g_csrc[ETOT];
__device__ int      g_cnt[NN];      // zero-init; re-zeroed by k_scan_scatter each call
__device__ int      g_rowstart[NN + 1];
__device__ int      g_wptr[NN];
__device__ unsigned g_barrier;      // monotonic grid-barrier counter (replay-safe)
__device__ float    g_xw1[NN * 128];
__device__ float    g_as1[NN * 4];
__device__ float    g_ad1[NN * 4];
__device__ float    g_xw2[NN * 8];
__device__ float    g_as2[NN];
__device__ float    g_ad2[NN];

// ---------------- CSR build ------------------------------------------------
// edge_index is INT32 (JAX x64 disabled makes the reference's astype(int64) a no-op)
__global__ void k_edges(const int* __restrict__ ei, int E) {
    int i = blockIdx.x * blockDim.x + threadIdx.x;
    if (i >= E) return;
    atomicAdd(&g_cnt[ei[E + i]], 1);
}

// Fused scan + scatter (one launch). Phase 1: reset-free exclusive scan
// (block b re-sums all preceding counts: ~20MB coalesced L2 reads total).
// Grid barrier (monotonic counter, all 196 blocks co-resident -> safe).
// Phase 2: grid-stride scatter via atomic write pointers + g_cnt re-zero.
__global__ void k_scan_scatter(const int* __restrict__ ei, int E, int T, int N) {
    __shared__ int ws[8];
    __shared__ int s_off;
    int b = blockIdx.x, t = threadIdx.x, lane = t & 31, w = t >> 5;
    int base = b * 256;

    // ---- phase 1a: offset = counts of nodes [0, base) + base self loops
    int partial = 0;
    for (int j = t; j < base; j += 256) partial += g_cnt[j];
    #pragma unroll
    for (int o = 16; o; o >>= 1) partial += __shfl_xor_sync(0xffffffffu, partial, o);
    if (lane == 0) ws[w] = partial;
    __syncthreads();
    if (w == 0) {
        int s = (lane < 8) ? ws[lane] : 0;
        #pragma unroll
        for (int o = 4; o; o >>= 1) s += __shfl_xor_sync(0xffffffffu, s, o);
        if (lane == 0) s_off = s + base;
    }
    __syncthreads();
    int off = s_off;
    __syncthreads();                   // ws reuse fence

    // ---- phase 1b: exclusive scan of own 256-tile (count+1 per node)
    int i = base + t;
    int v = (i < N) ? (g_cnt[i] + 1) : 0;
    int x = v;
    #pragma unroll
    for (int o = 1; o < 32; o <<= 1) {
        int y = __shfl_up_sync(0xffffffffu, x, o);
        if (lane >= o) x += y;
    }
    if (lane == 31) ws[w] = x;
    __syncthreads();
    if (w == 0) {
        int s = (lane < 8) ? ws[lane] : 0;
        #pragma unroll
        for (int o = 1; o < 8; o <<= 1) {
            int y = __shfl_up_sync(0xffffffffu, s, o);
            if (lane >= o) s += y;
        }
        if (lane < 8) ws[lane] = s;
    }
    __syncthreads();
    int excl = off + (x - v) + (w ? ws[w - 1] : 0);
    if (i < N) { g_rowstart[i] = excl; g_wptr[i] = excl; }
    if (b == 0 && t == 0) g_rowstart[N] = T;

    // ---- grid barrier (monotonic; each invocation adds exactly gridDim)
    __threadfence();
    __syncthreads();
    if (t == 0) {
        unsigned gen = atomicAdd(&g_barrier, 1u);
        unsigned target = (gen / gridDim.x + 1u) * gridDim.x;
        while (*((volatile unsigned*)&g_barrier) < target) { }
    }
    __syncthreads();
    __threadfence();

    // ---- phase 2: re-zero counts + scatter edges (grid-stride)
    int stride = gridDim.x * blockDim.x;
    for (int j = base + t; j < N; j += stride) g_cnt[j] = 0;
    for (int j = base + t; j < T; j += stride) {
        int s, d;
        if (j < E) { s = ei[j]; d = ei[E + j]; }
        else       { s = d = j - E; }            // self loops
        int pos = atomicAdd(&g_wptr[d], 1);
        g_csrc[pos] = s;
    }
}

// ---------------- layer-1 GEMM: xw1 = x @ W1 (+ attention dots) ------------
// 256 threads/block, 128 nodes/block. W1 transposed in smem (pitch 132).
// Packed fma.rn.f32x2 (dual fp32 FMA) halves fma-pipe occupancy.
extern __shared__ float sm_g1[];
__global__ void k_gemm1(const float* __restrict__ x, const float* __restrict__ W1,
                        const float* __restrict__ as1, const float* __restrict__ ad1,
                        int N) {
    float* Wt = sm_g1;                 // 128 cols x pitch 132
    float* xs = sm_g1 + 128 * 132;     // 16 x 128
    int t = threadIdx.x;
    int col = t & 127, grp = t >> 7, lane = t & 31;
    for (int idx = t; idx < 128 * 128; idx += 256) {
        int k = idx >> 7, c = idx & 127;
        Wt[c * 132 + k] = W1[idx];
    }
    float at_s = as1[col], at_d = ad1[col];
    __syncthreads();

    int nb = blockIdx.x * 128;
    for (int b = 0; b < 8; b++) {
        int base = nb + b * 16;
        for (int idx = t; idx < 16 * 128; idx += 256) {
            int m = idx >> 7, k = idx & 127;
            int nn = base + m;
            xs[idx] = (nn < N) ? x[nn * 128 + k] : 0.f;
        }
        __syncthreads();
        const float* xg = xs + grp * 8 * 128;
        unsigned long long acc2[8];
        #pragma unroll
        for (int m = 0; m < 8; m++) acc2[m] = 0ull;   // (0.f, 0.f)
        for (int k = 0; k < 128; k += 4) {
            float4 wv = *(const float4*)&Wt[col * 132 + k];
            unsigned long long w01, w23;
            asm("mov.b64 %0,{%1,%2};" : "=l"(w01) : "f"(wv.x), "f"(wv.y));
            asm("mov.b64 %0,{%1,%2};" : "=l"(w23) : "f"(wv.z), "f"(wv.w));
            #pragma unroll
            for (int m = 0; m < 8; m++) {
                float4 xv = *(const float4*)&xg[m * 128 + k];
                unsigned long long x01, x23;
                asm("mov.b64 %0,{%1,%2};" : "=l"(x01) : "f"(xv.x), "f"(xv.y));
                asm("mov.b64 %0,{%1,%2};" : "=l"(x23) : "f"(xv.z), "f"(xv.w));
                asm("fma.rn.f32x2 %0,%1,%2,%3;"
                    : "=l"(acc2[m]) : "l"(x01), "l"(w01), "l"(acc2[m]));
                asm("fma.rn.f32x2 %0,%1,%2,%3;"
                    : "=l"(acc2[m]) : "l"(x23), "l"(w23), "l"(acc2[m]));
            }
        }
        int n0 = base + grp * 8;
        #pragma unroll
        for (int m = 0; m < 8; m++) {
            float lo, hi;
            asm("mov.b64 {%0,%1},%2;" : "=f"(lo), "=f"(hi) : "l"(acc2[m]));
            float accm = lo + hi;
            int n = n0 + m;
            float sv = accm * at_s, dv = accm * at_d;
            #pragma unroll
            for (int o = 16; o; o >>= 1) {
                sv += __shfl_down_sync(0xffffffffu, sv, o);
                dv += __shfl_down_sync(0xffffffffu, dv, o);
            }
            if (n < N) {
                g_xw1[n * 128 + col] = accm;
                if (lane == 0) {
                    int h = (t >> 5) & 3;
                    g_as1[n * 4 + h] = sv;
                    g_ad1[n * 4 + h] = dv;
                }
            }
        }
        __syncthreads();
    }
}

// ---------------- layer-1 gather: softmax + fused bias/relu/GEMM2 ----------
// one warp per destination node; lane owns 4 consecutive channels (one head).
// Unshifted softmax (e is O(10) for this data -> exp(e) safe in fp32); 4-edge
// manual unroll issues all index loads, then all value loads -> MLP ~9.
__global__ void k_gather1(const float* __restrict__ b1, const float* __restrict__ W2,
                          const float* __restrict__ as2v, const float* __restrict__ ad2v,
                          int N) {
    int t = threadIdx.x, lane = t & 31;
    int n = blockIdx.x * 8 + (t >> 5);
    if (n >= N) return;

    int c0 = lane * 4;          // flat channel base
    int h = lane >> 3;          // head index for these channels
    float4 wA[4], wB[4];
    #pragma unroll
    for (int j = 0; j < 4; j++) {
        wA[j] = *(const float4*)&W2[(c0 + j) * 8];
        wB[j] = *(const float4*)&W2[(c0 + j) * 8 + 4];
    }
    float4 b1v = *(const float4*)&b1[c0];
    float adh = g_ad1[n * 4 + h];

    float den = 0.f;
    float4 acc = make_float4(0.f, 0.f, 0.f, 0.f);
    int beg = g_rowstart[n], end = g_rowstart[n + 1];
    int i = beg;
    for (; i + 4 <= end; i += 4) {
        int s0 = g_csrc[i],     s1 = g_csrc[i + 1];
        int s2 = g_csrc[i + 2], s3 = g_csrc[i + 3];
        float a0 = g_as1[s0 * 4 + h], a1 = g_as1[s1 * 4 + h];
        float a2 = g_as1[s2 * 4 + h], a3 = g_as1[s3 * 4 + h];
        float4 x0 = *(const float4*)&g_xw1[s0 * 128 + c0];
        float4 x1 = *(const float4*)&g_xw1[s1 * 128 + c0];
        float4 x2 = *(const float4*)&g_xw1[s2 * 128 + c0];
        float4 x3 = *(const float4*)&g_xw1[s3 * 128 + c0];
        float e0 = a0 + adh, e1 = a1 + adh, e2 = a2 + adh, e3 = a3 + adh;
        e0 = fmaxf(e0, 0.f) + 0.2f * fminf(e0, 0.f);
        e1 = fmaxf(e1, 0.f) + 0.2f * fminf(e1, 0.f);
        e2 = fmaxf(e2, 0.f) + 0.2f * fminf(e2, 0.f);
        e3 = fmaxf(e3, 0.f) + 0.2f * fminf(e3, 0.f);
        float p0 = __expf(e0), p1 = __expf(e1);
        float p2 = __expf(e2), p3 = __expf(e3);
        den += (p0 + p1) + (p2 + p3);
        acc.x += p0 * x0.x + p1 * x1.x + p2 * x2.x + p3 * x3.x;
        acc.y += p0 * x0.y + p1 * x1.y + p2 * x2.y + p3 * x3.y;
        acc.z += p0 * x0.z + p1 * x1.z + p2 * x2.z + p3 * x3.z;
        acc.w += p0 * x0.w + p1 * x1.w + p2 * x2.w + p3 * x3.w;
    }
    for (; i < end; i++) {
        int s = g_csrc[i];
        float e = g_as1[s * 4 + h] + adh;
        e = fmaxf(e, 0.f) + 0.2f * fminf(e, 0.f);
        float p = __expf(e);
        float4 xv = *(const float4*)&g_xw1[s * 128 + c0];
        den += p;
        acc.x += p * xv.x; acc.y += p * xv.y;
        acc.z += p * xv.z; acc.w += p * xv.w;
    }

    float inv = 1.f / den;
    float hj[4];
    hj[0] = fmaxf(acc.x * inv + b1v.x, 0.f);
    hj[1] = fmaxf(acc.y * inv + b1v.y, 0.f);
    hj[2] = fmaxf(acc.z * inv + b1v.z, 0.f);
    hj[3] = fmaxf(acc.w * inv + b1v.w, 0.f);

    float4 pA = make_float4(0.f, 0.f, 0.f, 0.f);
    float4 pB = make_float4(0.f, 0.f, 0.f, 0.f);
    #pragma unroll
    for (int j = 0; j < 4; j++) {
        pA.x += hj[j] * wA[j].x;  pA.y += hj[j] * wA[j].y;
        pA.z += hj[j] * wA[j].z;  pA.w += hj[j] * wA[j].w;
        pB.x += hj[j] * wB[j].x;  pB.y += hj[j] * wB[j].y;
        pB.z += hj[j] * wB[j].z;  pB.w += hj[j] * wB[j].w;
    }
    #pragma unroll
    for (int o = 16; o; o >>= 1) {
        pA.x += __shfl_xor_sync(0xffffffffu, pA.x, o);
        pA.y += __shfl_xor_sync(0xffffffffu, pA.y, o);
        pA.z += __shfl_xor_sync(0xffffffffu, pA.z, o);
        pA.w += __shfl_xor_sync(0xffffffffu, pA.w, o);
        pB.x += __shfl_xor_sync(0xffffffffu, pB.x, o);
        pB.y += __shfl_xor_sync(0xffffffffu, pB.y, o);
        pB.z += __shfl_xor_sync(0xffffffffu, pB.z, o);
        pB.w += __shfl_xor_sync(0xffffffffu, pB.w, o);
    }
    if (lane == 0) {
        *(float4*)&g_xw2[n * 8]     = pA;
        *(float4*)&g_xw2[n * 8 + 4] = pB;
        float4 sA = *(const float4*)&as2v[0];
        float4 sB = *(const float4*)&as2v[4];
        float4 dA = *(const float4*)&ad2v[0];
        float4 dB = *(const float4*)&ad2v[4];
        g_as2[n] = pA.x * sA.x + pA.y * sA.y + pA.z * sA.z + pA.w * sA.w
                 + pB.x * sB.x + pB.y * sB.y + pB.z * sB.z + pB.w * sB.w;
        g_ad2[n] = pA.x * dA.x + pA.y * dA.y + pA.z * dA.z + pA.w * dA.w
                 + pB.x * dB.x + pB.y * dB.y + pB.z * dB.z + pB.w * dB.w;
    }
}

// ---------------- layer-2 gather + bias + log_softmax ----------------------
// 8 lanes per node; each lane handles a different edge in a chunk of 8.
// Unshifted softmax: 1 expf + 1 sub-warp sum per 8 edges.
__global__ void k_gather2(const float* __restrict__ b2, float* __restrict__ out, int N) {
    int t = blockIdx.x * blockDim.x + threadIdx.x;
    int n = t >> 3, sub = t & 7;
    if (n >= N) return;
    unsigned gm = 0xffu << ((threadIdx.x & 31) & 24);   // this 8-lane group's mask

    float adh = g_ad2[n];
    float den = 0.f, acc = 0.f;
    int beg = g_rowstart[n], end = g_rowstart[n + 1];
    for (int i = beg; i < end; i += 8) {
        int idx = i + sub;
        bool v = (idx < end);
        int s = v ? g_csrc[idx] : 0;
        float e = v ? (g_as2[s] + adh) : -1e30f;
        e = fmaxf(e, 0.f) + 0.2f * fminf(e, 0.f);
        float p = __expf(e);                       // 0 for invalid lanes
        float psum = p;
        #pragma unroll
        for (int o = 4; o; o >>= 1)
            psum += __shfl_xor_sync(gm, psum, o, 8);
        den += psum;
        #pragma unroll
        for (int jj = 0; jj < 8; jj++) {
            float pj = __shfl_sync(gm, p, jj, 8);
            int   sj = __shfl_sync(gm, s, jj, 8);
            acc += pj * g_xw2[sj * 8 + sub];
        }
    }
    float o = acc / den + b2[sub];
    float m8 = o;
    #pragma unroll
    for (int off = 4; off; off >>= 1)
        m8 = fmaxf(m8, __shfl_xor_sync(gm, m8, off, 8));
    float ex = __expf(o - m8), sum = ex;
    #pragma unroll
    for (int off = 4; off; off >>= 1)
        sum += __shfl_xor_sync(gm, sum, off, 8);
    out[n * 8 + sub] = o - m8 - logf(sum);
}

// ---------------- launch ---------------------------------------------------
extern "C" void kernel_launch(void* const* d_in, const int* in_sizes, int n_in,
                              void* d_out, int out_size) {
    const float* x   = (const float*)d_in[0];
    const int*   ei  = (const int*)d_in[1];        // int32! (JAX x64 disabled)
    const float* W1  = (const float*)d_in[2];
    const float* as1 = (const float*)d_in[3];
    const float* ad1 = (const float*)d_in[4];
    const float* b1  = (const float*)d_in[5];
    const float* W2  = (const float*)d_in[6];
    const float* as2 = (const float*)d_in[7];
    const float* ad2 = (const float*)d_in[8];
    const float* b2  = (const float*)d_in[9];

    int N = in_sizes[0] / 128;
    int E = in_sizes[1] / 2;
    int T = E + N;
    int nb = (N + 255) / 256;

    // fork: gemm1 (needs only raw inputs) runs concurrently with the CSR build.
    // Submission order (ncu profiles kernel #4): gemm1, edges, scan_scatter,
    // gather1 <- profiled, gather2.
    cudaStream_t s2;
    cudaEvent_t ev_fork, ev_join;
    cudaStreamCreateWithFlags(&s2, cudaStreamNonBlocking);
    cudaEventCreateWithFlags(&ev_fork, cudaEventDisableTiming);
    cudaEventCreateWithFlags(&ev_join, cudaEventDisableTiming);

    cudaEventRecord(ev_fork, 0);
    cudaStreamWaitEvent(s2, ev_fork, 0);

    int smem = (128 * 132 + 16 * 128) * (int)sizeof(float);
    cudaFuncSetAttribute(k_gemm1, cudaFuncAttributeMaxDynamicSharedMemorySize, smem);
    k_gemm1<<<(N + 127) / 128, 256, smem, s2>>>(x, W1, as1, ad1, N);
    cudaEventRecord(ev_join, s2);

    // CSR build on the default stream (g_cnt zero: static init on first call,
    // re-zeroed inside k_scan_scatter every call)
    k_edges<<<(E + 255) / 256, 256>>>(ei, E);
    k_scan_scatter<<<nb, 256>>>(ei, E, T, N);

    cudaStreamWaitEvent(0, ev_join, 0);     // join gemm1 before gather1
    k_gather1<<<(N + 7) / 8, 256>>>(b1, W2, as2, ad2, N);
    k_gather2<<<(N * 8 + 255) / 256, 256>>>(b2, (float*)d_out, N);

    cudaStreamDestroy(s2);
    cudaEventDestroy(ev_fork);
    cudaEventDestroy(ev_join);
}

// round 10
// speedup vs baseline: 1.1494x; 1.0762x over previous
#include <cuda_runtime.h>

#define NN 50000
#define EE 800000
#define ETOT (EE + NN)

// ---------------- scratch (static device arrays; no runtime allocation) ----
__device__ int      g_csrc[ETOT];
__device__ int      g_cnt[NN];      // zero-init; re-zeroed by k_scan_scatter each call
__device__ int      g_rowstart[NN + 1];
__device__ int      g_wptr[NN];
__device__ unsigned g_barrier;      // monotonic grid-barrier counter (replay-safe)
__device__ float    g_xw1[NN * 128];
__device__ float    g_as1[NN * 4];
__device__ float    g_ad1[NN * 4];
__device__ float    g_xw2[NN * 8];
__device__ float    g_as2[NN];
__device__ float    g_ad2[NN];

// ---------------- CSR build ------------------------------------------------
// edge_index is INT32 (JAX x64 disabled makes the reference's astype(int64) a no-op)
__global__ void k_edges(const int* __restrict__ ei, int E) {
    int i = blockIdx.x * blockDim.x + threadIdx.x;
    if (i >= E) return;
    atomicAdd(&g_cnt[ei[E + i]], 1);
}

// Fused scan + scatter (one launch). Phase 1: reset-free exclusive scan
// (block b re-sums all preceding counts: ~20MB coalesced L2 reads total).
// Grid barrier (monotonic counter, all 196 blocks co-resident -> safe).
// Phase 2: grid-stride scatter via atomic write pointers + g_cnt re-zero.
__global__ void k_scan_scatter(const int* __restrict__ ei, int E, int T, int N) {
    __shared__ int ws[8];
    __shared__ int s_off;
    int b = blockIdx.x, t = threadIdx.x, lane = t & 31, w = t >> 5;
    int base = b * 256;

    // ---- phase 1a: offset = counts of nodes [0, base) + base self loops
    int partial = 0;
    for (int j = t; j < base; j += 256) partial += g_cnt[j];
    #pragma unroll
    for (int o = 16; o; o >>= 1) partial += __shfl_xor_sync(0xffffffffu, partial, o);
    if (lane == 0) ws[w] = partial;
    __syncthreads();
    if (w == 0) {
        int s = (lane < 8) ? ws[lane] : 0;
        #pragma unroll
        for (int o = 4; o; o >>= 1) s += __shfl_xor_sync(0xffffffffu, s, o);
        if (lane == 0) s_off = s + base;
    }
    __syncthreads();
    int off = s_off;
    __syncthreads();                   // ws reuse fence

    // ---- phase 1b: exclusive scan of own 256-tile (count+1 per node)
    int i = base + t;
    int v = (i < N) ? (g_cnt[i] + 1) : 0;
    int x = v;
    #pragma unroll
    for (int o = 1; o < 32; o <<= 1) {
        int y = __shfl_up_sync(0xffffffffu, x, o);
        if (lane >= o) x += y;
    }
    if (lane == 31) ws[w] = x;
    __syncthreads();
    if (w == 0) {
        int s = (lane < 8) ? ws[lane] : 0;
        #pragma unroll
        for (int o = 1; o < 8; o <<= 1) {
            int y = __shfl_up_sync(0xffffffffu, s, o);
            if (lane >= o) s += y;
        }
        if (lane < 8) ws[lane] = s;
    }
    __syncthreads();
    int excl = off + (x - v) + (w ? ws[w - 1] : 0);
    if (i < N) { g_rowstart[i] = excl; g_wptr[i] = excl; }
    if (b == 0 && t == 0) g_rowstart[N] = T;

    // ---- grid barrier (monotonic; each invocation adds exactly gridDim)
    __threadfence();
    __syncthreads();
    if (t == 0) {
        unsigned gen = atomicAdd(&g_barrier, 1u);
        unsigned target = (gen / gridDim.x + 1u) * gridDim.x;
        while (*((volatile unsigned*)&g_barrier) < target) { }
    }
    __syncthreads();
    __threadfence();

    // ---- phase 2: re-zero counts + scatter edges (grid-stride)
    int stride = gridDim.x * blockDim.x;
    for (int j = base + t; j < N; j += stride) g_cnt[j] = 0;
    for (int j = base + t; j < T; j += stride) {
        int s, d;
        if (j < E) { s = ei[j]; d = ei[E + j]; }
        else       { s = d = j - E; }            // self loops
        int pos = atomicAdd(&g_wptr[d], 1);
        g_csrc[pos] = s;
    }
}

// ---------------- layer-1 GEMM: xw1 = x @ W1 (+ attention dots) ------------
// 256 threads/block, 128 nodes/block. W1 transposed in smem (pitch 132).
// Packed fma.rn.f32x2 (dual fp32 FMA) halves fma-pipe occupancy.
extern __shared__ float sm_g1[];
__global__ void k_gemm1(const float* __restrict__ x, const float* __restrict__ W1,
                        const float* __restrict__ as1, const float* __restrict__ ad1,
                        int N) {
    float* Wt = sm_g1;                 // 128 cols x pitch 132
    float* xs = sm_g1 + 128 * 132;     // 16 x 128
    int t = threadIdx.x;
    int col = t & 127, grp = t >> 7, lane = t & 31;
    for (int idx = t; idx < 128 * 128; idx += 256) {
        int k = idx >> 7, c = idx & 127;
        Wt[c * 132 + k] = W1[idx];
    }
    float at_s = as1[col], at_d = ad1[col];
    __syncthreads();

    int nb = blockIdx.x * 128;
    for (int b = 0; b < 8; b++) {
        int base = nb + b * 16;
        for (int idx = t; idx < 16 * 128; idx += 256) {
            int m = idx >> 7, k = idx & 127;
            int nn = base + m;
            xs[idx] = (nn < N) ? x[nn * 128 + k] : 0.f;
        }
        __syncthreads();
        const float* xg = xs + grp * 8 * 128;
        unsigned long long acc2[8];
        #pragma unroll
        for (int m = 0; m < 8; m++) acc2[m] = 0ull;   // (0.f, 0.f)
        for (int k = 0; k < 128; k += 4) {
            float4 wv = *(const float4*)&Wt[col * 132 + k];
            unsigned long long w01, w23;
            asm("mov.b64 %0,{%1,%2};" : "=l"(w01) : "f"(wv.x), "f"(wv.y));
            asm("mov.b64 %0,{%1,%2};" : "=l"(w23) : "f"(wv.z), "f"(wv.w));
            #pragma unroll
            for (int m = 0; m < 8; m++) {
                float4 xv = *(const float4*)&xg[m * 128 + k];
                unsigned long long x01, x23;
                asm("mov.b64 %0,{%1,%2};" : "=l"(x01) : "f"(xv.x), "f"(xv.y));
                asm("mov.b64 %0,{%1,%2};" : "=l"(x23) : "f"(xv.z), "f"(xv.w));
                asm("fma.rn.f32x2 %0,%1,%2,%3;"
                    : "=l"(acc2[m]) : "l"(x01), "l"(w01), "l"(acc2[m]));
                asm("fma.rn.f32x2 %0,%1,%2,%3;"
                    : "=l"(acc2[m]) : "l"(x23), "l"(w23), "l"(acc2[m]));
            }
        }
        int n0 = base + grp * 8;
        #pragma unroll
        for (int m = 0; m < 8; m++) {
            float lo, hi;
            asm("mov.b64 {%0,%1},%2;" : "=f"(lo), "=f"(hi) : "l"(acc2[m]));
            float accm = lo + hi;
            int n = n0 + m;
            float sv = accm * at_s, dv = accm * at_d;
            #pragma unroll
            for (int o = 16; o; o >>= 1) {
                sv += __shfl_down_sync(0xffffffffu, sv, o);
                dv += __shfl_down_sync(0xffffffffu, dv, o);
            }
            if (n < N) {
                g_xw1[n * 128 + col] = accm;
                if (lane == 0) {
                    int h = (t >> 5) & 3;
                    g_as1[n * 4 + h] = sv;
                    g_ad1[n * 4 + h] = dv;
                }
            }
        }
        __syncthreads();
    }
}

// ---------------- layer-1 gather: softmax + fused bias/relu/GEMM2 ----------
// One warp per destination node; lane owns 4 consecutive channels (one head).
// __launch_bounds__(256, 5) caps regs (~51) -> 62.5% occupancy (was 72 regs /
// 32.8%). ALL epilogue weight loads (W2, b1, as2, ad2) moved AFTER the edge
// loop so they are not live across it. Unroll-4 load batching -> MLP ~9.
__global__ void __launch_bounds__(256, 5)
k_gather1(const float* __restrict__ b1, const float* __restrict__ W2,
          const float* __restrict__ as2v, const float* __restrict__ ad2v,
          int N) {
    int t = threadIdx.x, lane = t & 31;
    int n = blockIdx.x * 8 + (t >> 5);
    if (n >= N) return;

    int c0 = lane * 4;          // flat channel base
    int h = lane >> 3;          // head index for these channels
    float adh = g_ad1[n * 4 + h];

    float den = 0.f;
    float4 acc = make_float4(0.f, 0.f, 0.f, 0.f);
    int beg = g_rowstart[n], end = g_rowstart[n + 1];
    int i = beg;
    for (; i + 4 <= end; i += 4) {
        int s0 = g_csrc[i],     s1 = g_csrc[i + 1];
        int s2 = g_csrc[i + 2], s3 = g_csrc[i + 3];
        float a0 = g_as1[s0 * 4 + h], a1 = g_as1[s1 * 4 + h];
        float a2 = g_as1[s2 * 4 + h], a3 = g_as1[s3 * 4 + h];
        float4 x0 = *(const float4*)&g_xw1[s0 * 128 + c0];
        float4 x1 = *(const float4*)&g_xw1[s1 * 128 + c0];
        float4 x2 = *(const float4*)&g_xw1[s2 * 128 + c0];
        float4 x3 = *(const float4*)&g_xw1[s3 * 128 + c0];
        float e0 = a0 + adh, e1 = a1 + adh, e2 = a2 + adh, e3 = a3 + adh;
        e0 = fmaxf(e0, 0.f) + 0.2f * fminf(e0, 0.f);
        e1 = fmaxf(e1, 0.f) + 0.2f * fminf(e1, 0.f);
        e2 = fmaxf(e2, 0.f) + 0.2f * fminf(e2, 0.f);
        e3 = fmaxf(e3, 0.f) + 0.2f * fminf(e3, 0.f);
        float p0 = __expf(e0), p1 = __expf(e1);
        float p2 = __expf(e2), p3 = __expf(e3);
        den += (p0 + p1) + (p2 + p3);
        acc.x += p0 * x0.x + p1 * x1.x + p2 * x2.x + p3 * x3.x;
        acc.y += p0 * x0.y + p1 * x1.y + p2 * x2.y + p3 * x3.y;
        acc.z += p0 * x0.z + p1 * x1.z + p2 * x2.z + p3 * x3.z;
        acc.w += p0 * x0.w + p1 * x1.w + p2 * x2.w + p3 * x3.w;
    }
    for (; i < end; i++) {
        int s = g_csrc[i];
        float e = g_as1[s * 4 + h] + adh;
        e = fmaxf(e, 0.f) + 0.2f * fminf(e, 0.f);
        float p = __expf(e);
        float4 xv = *(const float4*)&g_xw1[s * 128 + c0];
        den += p;
        acc.x += p * xv.x; acc.y += p * xv.y;
        acc.z += p * xv.z; acc.w += p * xv.w;
    }

    // ---- epilogue (weights loaded only now; not live during the loop) ----
    float4 b1v = *(const float4*)&b1[c0];
    float inv = 1.f / den;
    float hj[4];
    hj[0] = fmaxf(acc.x * inv + b1v.x, 0.f);
    hj[1] = fmaxf(acc.y * inv + b1v.y, 0.f);
    hj[2] = fmaxf(acc.z * inv + b1v.z, 0.f);
    hj[3] = fmaxf(acc.w * inv + b1v.w, 0.f);

    float4 pA = make_float4(0.f, 0.f, 0.f, 0.f);
    float4 pB = make_float4(0.f, 0.f, 0.f, 0.f);
    #pragma unroll
    for (int j = 0; j < 4; j++) {
        float4 wAj = *(const float4*)&W2[(c0 + j) * 8];
        float4 wBj = *(const float4*)&W2[(c0 + j) * 8 + 4];
        pA.x += hj[j] * wAj.x;  pA.y += hj[j] * wAj.y;
        pA.z += hj[j] * wAj.z;  pA.w += hj[j] * wAj.w;
        pB.x += hj[j] * wBj.x;  pB.y += hj[j] * wBj.y;
        pB.z += hj[j] * wBj.z;  pB.w += hj[j] * wBj.w;
    }
    #pragma unroll
    for (int o = 16; o; o >>= 1) {
        pA.x += __shfl_xor_sync(0xffffffffu, pA.x, o);
        pA.y += __shfl_xor_sync(0xffffffffu, pA.y, o);
        pA.z += __shfl_xor_sync(0xffffffffu, pA.z, o);
        pA.w += __shfl_xor_sync(0xffffffffu, pA.w, o);
        pB.x += __shfl_xor_sync(0xffffffffu, pB.x, o);
        pB.y += __shfl_xor_sync(0xffffffffu, pB.y, o);
        pB.z += __shfl_xor_sync(0xffffffffu, pB.z, o);
        pB.w += __shfl_xor_sync(0xffffffffu, pB.w, o);
    }
    if (lane == 0) {
        *(float4*)&g_xw2[n * 8]     = pA;
        *(float4*)&g_xw2[n * 8 + 4] = pB;
        float4 sA = *(const float4*)&as2v[0];
        float4 sB = *(const float4*)&as2v[4];
        float4 dA = *(const float4*)&ad2v[0];
        float4 dB = *(const float4*)&ad2v[4];
        g_as2[n] = pA.x * sA.x + pA.y * sA.y + pA.z * sA.z + pA.w * sA.w
                 + pB.x * sB.x + pB.y * sB.y + pB.z * sB.z + pB.w * sB.w;
        g_ad2[n] = pA.x * dA.x + pA.y * dA.y + pA.z * dA.z + pA.w * dA.w
                 + pB.x * dB.x + pB.y * dB.y + pB.z * dB.z + pB.w * dB.w;
    }
}

// ---------------- layer-2 gather + bias + log_softmax ----------------------
// 8 lanes per node; each lane handles a different edge in a chunk of 8.
// Unshifted softmax: 1 expf + 1 sub-warp sum per 8 edges.
__global__ void k_gather2(const float* __restrict__ b2, float* __restrict__ out, int N) {
    int t = blockIdx.x * blockDim.x + threadIdx.x;
    int n = t >> 3, sub = t & 7;
    if (n >= N) return;
    unsigned gm = 0xffu << ((threadIdx.x & 31) & 24);   // this 8-lane group's mask

    float adh = g_ad2[n];
    float den = 0.f, acc = 0.f;
    int beg = g_rowstart[n], end = g_rowstart[n + 1];
    for (int i = beg; i < end; i += 8) {
        int idx = i + sub;
        bool v = (idx < end);
        int s = v ? g_csrc[idx] : 0;
        float e = v ? (g_as2[s] + adh) : -1e30f;
        e = fmaxf(e, 0.f) + 0.2f * fminf(e, 0.f);
        float p = __expf(e);                       // 0 for invalid lanes
        float psum = p;
        #pragma unroll
        for (int o = 4; o; o >>= 1)
            psum += __shfl_xor_sync(gm, psum, o, 8);
        den += psum;
        #pragma unroll
        for (int jj = 0; jj < 8; jj++) {
            float pj = __shfl_sync(gm, p, jj, 8);
            int   sj = __shfl_sync(gm, s, jj, 8);
            acc += pj * g_xw2[sj * 8 + sub];
        }
    }
    float o = acc / den + b2[sub];
    float m8 = o;
    #pragma unroll
    for (int off = 4; off; off >>= 1)
        m8 = fmaxf(m8, __shfl_xor_sync(gm, m8, off, 8));
    float ex = __expf(o - m8), sum = ex;
    #pragma unroll
    for (int off = 4; off; off >>= 1)
        sum += __shfl_xor_sync(gm, sum, off, 8);
    out[n * 8 + sub] = o - m8 - logf(sum);
}

// ---------------- launch ---------------------------------------------------
extern "C" void kernel_launch(void* const* d_in, const int* in_sizes, int n_in,
                              void* d_out, int out_size) {
    const float* x   = (const float*)d_in[0];
    const int*   ei  = (const int*)d_in[1];        // int32! (JAX x64 disabled)
    const float* W1  = (const float*)d_in[2];
    const float* as1 = (const float*)d_in[3];
    const float* ad1 = (const float*)d_in[4];
    const float* b1  = (const float*)d_in[5];
    const float* W2  = (const float*)d_in[6];
    const float* as2 = (const float*)d_in[7];
    const float* ad2 = (const float*)d_in[8];
    const float* b2  = (const float*)d_in[9];

    int N = in_sizes[0] / 128;
    int E = in_sizes[1] / 2;
    int T = E + N;
    int nb = (N + 255) / 256;

    // fork: gemm1 (needs only raw inputs) runs concurrently with the CSR build.
    // Submission order (ncu profiles kernel #4): gemm1, edges, scan_scatter,
    // gather1 <- profiled, gather2.
    cudaStream_t s2;
    cudaEvent_t ev_fork, ev_join;
    cudaStreamCreateWithFlags(&s2, cudaStreamNonBlocking);
    cudaEventCreateWithFlags(&ev_fork, cudaEventDisableTiming);
    cudaEventCreateWithFlags(&ev_join, cudaEventDisableTiming);

    cudaEventRecord(ev_fork, 0);
    cudaStreamWaitEvent(s2, ev_fork, 0);

    int smem = (128 * 132 + 16 * 128) * (int)sizeof(float);
    cudaFuncSetAttribute(k_gemm1, cudaFuncAttributeMaxDynamicSharedMemorySize, smem);
    k_gemm1<<<(N + 127) / 128, 256, smem, s2>>>(x, W1, as1, ad1, N);
    cudaEventRecord(ev_join, s2);

    // CSR build on the default stream (g_cnt zero: static init on first call,
    // re-zeroed inside k_scan_scatter every call)
    k_edges<<<(E + 255) / 256, 256>>>(ei, E);
    k_scan_scatter<<<nb, 256>>>(ei, E, T, N);

    cudaStreamWaitEvent(0, ev_join, 0);     // join gemm1 before gather1
    k_gather1<<<(N + 7) / 8, 256>>>(b1, W2, as2, ad2, N);
    k_gather2<<<(N * 8 + 255) / 256, 256>>>(b2, (float*)d_out, N);

    cudaStreamDestroy(s2);
    cudaEventDestroy(ev_fork);
    cudaEventDestroy(ev_join);
}

// round 11
// speedup vs baseline: 1.2947x; 1.1265x over previous
#include <cuda_runtime.h>
#include <cuda_fp16.h>

#define NN 50000
#define EE 800000
#define ETOT (EE + NN)

// ---------------- scratch (static device arrays; no runtime allocation) ----
__device__ int      g_csrc[ETOT];
__device__ int      g_cnt[NN];      // zero-init; re-zeroed by k_scan_scatter each call
__device__ int      g_rowstart[NN + 1];
__device__ int      g_wptr[NN];
__device__ unsigned g_barrier;      // monotonic grid-barrier counter (replay-safe)
__device__ __half   g_xw1h[NN * 128];   // fp16 features (read 17x by gather1)
__device__ float    g_as1[NN * 4];
__device__ float    g_ad1[NN * 4];
__device__ float    g_xw2[NN * 8];
__device__ float    g_as2[NN];
__device__ float    g_ad2[NN];

struct h4 { __half2 a, b; };        // 8-byte vector of 4 halves

// ---------------- CSR build ------------------------------------------------
// edge_index is INT32 (JAX x64 disabled makes the reference's astype(int64) a no-op)
__global__ void k_edges(const int* __restrict__ ei, int E) {
    int i = blockIdx.x * blockDim.x + threadIdx.x;
    if (i >= E) return;
    atomicAdd(&g_cnt[ei[E + i]], 1);
}

// Fused scan + scatter (one launch). Phase 1: reset-free exclusive scan.
// Grid barrier (monotonic counter, all 196 blocks co-resident -> safe).
// Phase 2: grid-stride scatter via atomic write pointers + g_cnt re-zero.
__global__ void k_scan_scatter(const int* __restrict__ ei, int E, int T, int N) {
    __shared__ int ws[8];
    __shared__ int s_off;
    int b = blockIdx.x, t = threadIdx.x, lane = t & 31, w = t >> 5;
    int base = b * 256;

    // ---- phase 1a: offset = counts of nodes [0, base) + base self loops
    int partial = 0;
    for (int j = t; j < base; j += 256) partial += g_cnt[j];
    #pragma unroll
    for (int o = 16; o; o >>= 1) partial += __shfl_xor_sync(0xffffffffu, partial, o);
    if (lane == 0) ws[w] = partial;
    __syncthreads();
    if (w == 0) {
        int s = (lane < 8) ? ws[lane] : 0;
        #pragma unroll
        for (int o = 4; o; o >>= 1) s += __shfl_xor_sync(0xffffffffu, s, o);
        if (lane == 0) s_off = s + base;
    }
    __syncthreads();
    int off = s_off;
    __syncthreads();                   // ws reuse fence

    // ---- phase 1b: exclusive scan of own 256-tile (count+1 per node)
    int i = base + t;
    int v = (i < N) ? (g_cnt[i] + 1) : 0;
    int x = v;
    #pragma unroll
    for (int o = 1; o < 32; o <<= 1) {
        int y = __shfl_up_sync(0xffffffffu, x, o);
        if (lane >= o) x += y;
    }
    if (lane == 31) ws[w] = x;
    __syncthreads();
    if (w == 0) {
        int s = (lane < 8) ? ws[lane] : 0;
        #pragma unroll
        for (int o = 1; o < 8; o <<= 1) {
            int y = __shfl_up_sync(0xffffffffu, s, o);
            if (lane >= o) s += y;
        }
        if (lane < 8) ws[lane] = s;
    }
    __syncthreads();
    int excl = off + (x - v) + (w ? ws[w - 1] : 0);
    if (i < N) { g_rowstart[i] = excl; g_wptr[i] = excl; }
    if (b == 0 && t == 0) g_rowstart[N] = T;

    // ---- grid barrier (monotonic; each invocation adds exactly gridDim)
    __threadfence();
    __syncthreads();
    if (t == 0) {
        unsigned gen = atomicAdd(&g_barrier, 1u);
        unsigned target = (gen / gridDim.x + 1u) * gridDim.x;
        while (*((volatile unsigned*)&g_barrier) < target) { }
    }
    __syncthreads();
    __threadfence();

    // ---- phase 2: re-zero counts + scatter edges (grid-stride)
    int stride = gridDim.x * blockDim.x;
    for (int j = base + t; j < N; j += stride) g_cnt[j] = 0;
    for (int j = base + t; j < T; j += stride) {
        int s, d;
        if (j < E) { s = ei[j]; d = ei[E + j]; }
        else       { s = d = j - E; }            // self loops
        int pos = atomicAdd(&g_wptr[d], 1);
        g_csrc[pos] = s;
    }
}

// ---------------- layer-1 GEMM: xw1 = x @ W1 (+ attention dots) ------------
// 256 threads/block, 128 nodes/block. W1 transposed in smem (pitch 132).
// Packed fma.rn.f32x2 (dual fp32 FMA). Features stored fp16 (halves the
// gather1 read stream); attention dots stay fp32 (exact softmax weights).
extern __shared__ float sm_g1[];
__global__ void k_gemm1(const float* __restrict__ x, const float* __restrict__ W1,
                        const float* __restrict__ as1, const float* __restrict__ ad1,
                        int N) {
    float* Wt = sm_g1;                 // 128 cols x pitch 132
    float* xs = sm_g1 + 128 * 132;     // 16 x 128
    int t = threadIdx.x;
    int col = t & 127, grp = t >> 7, lane = t & 31;
    for (int idx = t; idx < 128 * 128; idx += 256) {
        int k = idx >> 7, c = idx & 127;
        Wt[c * 132 + k] = W1[idx];
    }
    float at_s = as1[col], at_d = ad1[col];
    __syncthreads();

    int nb = blockIdx.x * 128;
    for (int b = 0; b < 8; b++) {
        int base = nb + b * 16;
        for (int idx = t; idx < 16 * 128; idx += 256) {
            int m = idx >> 7, k = idx & 127;
            int nn = base + m;
            xs[idx] = (nn < N) ? x[nn * 128 + k] : 0.f;
        }
        __syncthreads();
        const float* xg = xs + grp * 8 * 128;
        unsigned long long acc2[8];
        #pragma unroll
        for (int m = 0; m < 8; m++) acc2[m] = 0ull;   // (0.f, 0.f)
        for (int k = 0; k < 128; k += 4) {
            float4 wv = *(const float4*)&Wt[col * 132 + k];
            unsigned long long w01, w23;
            asm("mov.b64 %0,{%1,%2};" : "=l"(w01) : "f"(wv.x), "f"(wv.y));
            asm("mov.b64 %0,{%1,%2};" : "=l"(w23) : "f"(wv.z), "f"(wv.w));
            #pragma unroll
            for (int m = 0; m < 8; m++) {
                float4 xv = *(const float4*)&xg[m * 128 + k];
                unsigned long long x01, x23;
                asm("mov.b64 %0,{%1,%2};" : "=l"(x01) : "f"(xv.x), "f"(xv.y));
                asm("mov.b64 %0,{%1,%2};" : "=l"(x23) : "f"(xv.z), "f"(xv.w));
                asm("fma.rn.f32x2 %0,%1,%2,%3;"
                    : "=l"(acc2[m]) : "l"(x01), "l"(w01), "l"(acc2[m]));
                asm("fma.rn.f32x2 %0,%1,%2,%3;"
                    : "=l"(acc2[m]) : "l"(x23), "l"(w23), "l"(acc2[m]));
            }
        }
        int n0 = base + grp * 8;
        #pragma unroll
        for (int m = 0; m < 8; m++) {
            float lo, hi;
            asm("mov.b64 {%0,%1},%2;" : "=f"(lo), "=f"(hi) : "l"(acc2[m]));
            float accm = lo + hi;
            int n = n0 + m;
            float sv = accm * at_s, dv = accm * at_d;
            #pragma unroll
            for (int o = 16; o; o >>= 1) {
                sv += __shfl_down_sync(0xffffffffu, sv, o);
                dv += __shfl_down_sync(0xffffffffu, dv, o);
            }
            if (n < N) {
                g_xw1h[n * 128 + col] = __float2half(accm);
                if (lane == 0) {
                    int h = (t >> 5) & 3;
                    g_as1[n * 4 + h] = sv;
                    g_ad1[n * 4 + h] = dv;
                }
            }
        }
        __syncthreads();
    }
}

// ---------------- layer-1 gather: softmax + fused bias/relu/GEMM2 ----------
// Fixed single-wave grid (740 blocks = 5/SM); warp g statically interleaves
// nodes g, g+W, ... (~8 nodes/warp -> warp-duration CV ~9% vs 24% per-node).
// Lane owns 4 consecutive channels (one head). fp16 feature loads (8B/lane,
// 2 L1 lines per edge vs 4 for fp32). Epilogue loads after the edge loop.
__global__ void __launch_bounds__(256, 5)
k_gather1(const float* __restrict__ b1, const float* __restrict__ W2,
          const float* __restrict__ as2v, const float* __restrict__ ad2v,
          int N) {
    int t = threadIdx.x, lane = t & 31;
    int gw = (blockIdx.x * blockDim.x + t) >> 5;       // global warp id
    int W = (gridDim.x * blockDim.x) >> 5;             // total warps

    int c0 = lane * 4;          // flat channel base
    int h = lane >> 3;          // head index for these channels

    for (int n = gw; n < N; n += W) {
        float adh = g_ad1[n * 4 + h];
        float den = 0.f;
        float4 acc = make_float4(0.f, 0.f, 0.f, 0.f);
        int beg = g_rowstart[n], end = g_rowstart[n + 1];
        int i = beg;
        for (; i + 4 <= end; i += 4) {
            int s0 = g_csrc[i],     s1 = g_csrc[i + 1];
            int s2 = g_csrc[i + 2], s3 = g_csrc[i + 3];
            float a0 = g_as1[s0 * 4 + h], a1 = g_as1[s1 * 4 + h];
            float a2 = g_as1[s2 * 4 + h], a3 = g_as1[s3 * 4 + h];
            h4 v0 = *(const h4*)&g_xw1h[s0 * 128 + c0];
            h4 v1 = *(const h4*)&g_xw1h[s1 * 128 + c0];
            h4 v2 = *(const h4*)&g_xw1h[s2 * 128 + c0];
            h4 v3 = *(const h4*)&g_xw1h[s3 * 128 + c0];
            float e0 = a0 + adh, e1 = a1 + adh, e2 = a2 + adh, e3 = a3 + adh;
            e0 = fmaxf(e0, 0.f) + 0.2f * fminf(e0, 0.f);
            e1 = fmaxf(e1, 0.f) + 0.2f * fminf(e1, 0.f);
            e2 = fmaxf(e2, 0.f) + 0.2f * fminf(e2, 0.f);
            e3 = fmaxf(e3, 0.f) + 0.2f * fminf(e3, 0.f);
            float p0 = __expf(e0), p1 = __expf(e1);
            float p2 = __expf(e2), p3 = __expf(e3);
            den += (p0 + p1) + (p2 + p3);
            float2 f0a = __half22float2(v0.a), f0b = __half22float2(v0.b);
            float2 f1a = __half22float2(v1.a), f1b = __half22float2(v1.b);
            float2 f2a = __half22float2(v2.a), f2b = __half22float2(v2.b);
            float2 f3a = __half22float2(v3.a), f3b = __half22float2(v3.b);
            acc.x += p0 * f0a.x + p1 * f1a.x + p2 * f2a.x + p3 * f3a.x;
            acc.y += p0 * f0a.y + p1 * f1a.y + p2 * f2a.y + p3 * f3a.y;
            acc.z += p0 * f0b.x + p1 * f1b.x + p2 * f2b.x + p3 * f3b.x;
            acc.w += p0 * f0b.y + p1 * f1b.y + p2 * f2b.y + p3 * f3b.y;
        }
        for (; i < end; i++) {
            int s = g_csrc[i];
            float e = g_as1[s * 4 + h] + adh;
            e = fmaxf(e, 0.f) + 0.2f * fminf(e, 0.f);
            float p = __expf(e);
            h4 v = *(const h4*)&g_xw1h[s * 128 + c0];
            float2 fa = __half22float2(v.a), fb = __half22float2(v.b);
            den += p;
            acc.x += p * fa.x; acc.y += p * fa.y;
            acc.z += p * fb.x; acc.w += p * fb.y;
        }

        // ---- epilogue (weights loaded only now; L1/L2-hot across nodes) ----
        float4 b1v = *(const float4*)&b1[c0];
        float inv = 1.f / den;
        float hj[4];
        hj[0] = fmaxf(acc.x * inv + b1v.x, 0.f);
        hj[1] = fmaxf(acc.y * inv + b1v.y, 0.f);
        hj[2] = fmaxf(acc.z * inv + b1v.z, 0.f);
        hj[3] = fmaxf(acc.w * inv + b1v.w, 0.f);

        float4 pA = make_float4(0.f, 0.f, 0.f, 0.f);
        float4 pB = make_float4(0.f, 0.f, 0.f, 0.f);
        #pragma unroll
        for (int j = 0; j < 4; j++) {
            float4 wAj = *(const float4*)&W2[(c0 + j) * 8];
            float4 wBj = *(const float4*)&W2[(c0 + j) * 8 + 4];
            pA.x += hj[j] * wAj.x;  pA.y += hj[j] * wAj.y;
            pA.z += hj[j] * wAj.z;  pA.w += hj[j] * wAj.w;
            pB.x += hj[j] * wBj.x;  pB.y += hj[j] * wBj.y;
            pB.z += hj[j] * wBj.z;  pB.w += hj[j] * wBj.w;
        }
        #pragma unroll
        for (int o = 16; o; o >>= 1) {
            pA.x += __shfl_xor_sync(0xffffffffu, pA.x, o);
            pA.y += __shfl_xor_sync(0xffffffffu, pA.y, o);
            pA.z += __shfl_xor_sync(0xffffffffu, pA.z, o);
            pA.w += __shfl_xor_sync(0xffffffffu, pA.w, o);
            pB.x += __shfl_xor_sync(0xffffffffu, pB.x, o);
            pB.y += __shfl_xor_sync(0xffffffffu, pB.y, o);
            pB.z += __shfl_xor_sync(0xffffffffu, pB.z, o);
            pB.w += __shfl_xor_sync(0xffffffffu, pB.w, o);
        }
        if (lane == 0) {
            *(float4*)&g_xw2[n * 8]     = pA;
            *(float4*)&g_xw2[n * 8 + 4] = pB;
            float4 sA = *(const float4*)&as2v[0];
            float4 sB = *(const float4*)&as2v[4];
            float4 dA = *(const float4*)&ad2v[0];
            float4 dB = *(const float4*)&ad2v[4];
            g_as2[n] = pA.x * sA.x + pA.y * sA.y + pA.z * sA.z + pA.w * sA.w
                     + pB.x * sB.x + pB.y * sB.y + pB.z * sB.z + pB.w * sB.w;
            g_ad2[n] = pA.x * dA.x + pA.y * dA.y + pA.z * dA.z + pA.w * dA.w
                     + pB.x * dB.x + pB.y * dB.y + pB.z * dB.z + pB.w * dB.w;
        }
    }
}

// ---------------- layer-2 gather + bias + log_softmax ----------------------
// Fixed grid, static interleave of 8-lane node groups. Unshifted softmax:
// 1 expf + 1 sub-warp sum per 8 edges.
__global__ void k_gather2(const float* __restrict__ b2, float* __restrict__ out, int N) {
    int t = blockIdx.x * blockDim.x + threadIdx.x;
    int sub = t & 7;
    int gid = t >> 3;                         // global 8-lane group id
    int G = (gridDim.x * blockDim.x) >> 3;    // total groups
    unsigned gm = 0xffu << ((threadIdx.x & 31) & 24);

    for (int n = gid; n < N; n += G) {
        float adh = g_ad2[n];
        float den = 0.f, acc = 0.f;
        int beg = g_rowstart[n], end = g_rowstart[n + 1];
        for (int i = beg; i < end; i += 8) {
            int idx = i + sub;
            bool v = (idx < end);
            int s = v ? g_csrc[idx] : 0;
            float e = v ? (g_as2[s] + adh) : -1e30f;
            e = fmaxf(e, 0.f) + 0.2f * fminf(e, 0.f);
            float p = __expf(e);                   // 0 for invalid lanes
            float psum = p;
            #pragma unroll
            for (int o = 4; o; o >>= 1)
                psum += __shfl_xor_sync(gm, psum, o, 8);
            den += psum;
            #pragma unroll
            for (int jj = 0; jj < 8; jj++) {
                float pj = __shfl_sync(gm, p, jj, 8);
                int   sj = __shfl_sync(gm, s, jj, 8);
                acc += pj * g_xw2[sj * 8 + sub];
            }
        }
        float o = acc / den + b2[sub];
        float m8 = o;
        #pragma unroll
        for (int off = 4; off; off >>= 1)
            m8 = fmaxf(m8, __shfl_xor_sync(gm, m8, off, 8));
        float ex = __expf(o - m8), sum = ex;
        #pragma unroll
        for (int off = 4; off; off >>= 1)
            sum += __shfl_xor_sync(gm, sum, off, 8);
        out[n * 8 + sub] = o - m8 - logf(sum);
    }
}

// ---------------- launch ---------------------------------------------------
extern "C" void kernel_launch(void* const* d_in, const int* in_sizes, int n_in,
                              void* d_out, int out_size) {
    const float* x   = (const float*)d_in[0];
    const int*   ei  = (const int*)d_in[1];        // int32! (JAX x64 disabled)
    const float* W1  = (const float*)d_in[2];
    const float* as1 = (const float*)d_in[3];
    const float* ad1 = (const float*)d_in[4];
    const float* b1  = (const float*)d_in[5];
    const float* W2  = (const float*)d_in[6];
    const float* as2 = (const float*)d_in[7];
    const float* ad2 = (const float*)d_in[8];
    const float* b2  = (const float*)d_in[9];

    int N = in_sizes[0] / 128;
    int E = in_sizes[1] / 2;
    int T = E + N;
    int nb = (N + 255) / 256;

    // fork: gemm1 (needs only raw inputs) runs concurrently with the CSR build.
    // Submission order (ncu profiles kernel #4): gemm1, edges, scan_scatter,
    // gather1 <- profiled, gather2.
    cudaStream_t s2;
    cudaEvent_t ev_fork, ev_join;
    cudaStreamCreateWithFlags(&s2, cudaStreamNonBlocking);
    cudaEventCreateWithFlags(&ev_fork, cudaEventDisableTiming);
    cudaEventCreateWithFlags(&ev_join, cudaEventDisableTiming);

    cudaEventRecord(ev_fork, 0);
    cudaStreamWaitEvent(s2, ev_fork, 0);

    int smem = (128 * 132 + 16 * 128) * (int)sizeof(float);
    cudaFuncSetAttribute(k_gemm1, cudaFuncAttributeMaxDynamicSharedMemorySize, smem);
    k_gemm1<<<(N + 127) / 128, 256, smem, s2>>>(x, W1, as1, ad1, N);
    cudaEventRecord(ev_join, s2);

    // CSR build on the default stream (g_cnt zero: static init on first call,
    // re-zeroed inside k_scan_scatter every call)
    k_edges<<<(E + 255) / 256, 256>>>(ei, E);
    k_scan_scatter<<<nb, 256>>>(ei, E, T, N);

    cudaStreamWaitEvent(0, ev_join, 0);     // join gemm1 before gather1
    k_gather1<<<740, 256>>>(b1, W2, as2, ad2, N);     // one wave: 5 blocks/SM
    k_gather2<<<592, 256>>>(b2, (float*)d_out, N);

    cudaStreamDestroy(s2);
    cudaEventDestroy(ev_fork);
    cudaEventDestroy(ev_join);
}